// round 15
// baseline (speedup 1.0000x reference)
#include <cuda_runtime.h>
#include <cstdint>

static constexpr int NL  = 4096;     // coarse points
static constexpr int NH  = 16384;    // fine points
static constexpr int NF  = 256;      // features
static constexpr int PPB = 112;      // fine points per block
static constexpr int TPB = 896;      // 28 warps; warp w owns points 4w..4w+3
static constexpr int GRID = (NH + PPB - 1) / PPB;  // 147
static constexpr int SMEM_BYTES = NL * 16;         // 64 KB sorted table

__device__ float4 g_SL[NL];   // sorted by w: (-2x, -2y, -2z, w=|l|^2)
__device__ int    g_sid[NL];  // sorted pos -> original coarse index

// ---------- kernel 1: bitonic sort candidates by |l|^2 ----------
__global__ __launch_bounds__(1024, 1)
void k_sort(const float* __restrict__ pl) {
    __shared__ unsigned long long sk[NL];   // 32 KB: key = (bits(w)<<32)|idx
    const int t = threadIdx.x;
    for (int i = t; i < NL; i += 1024) {
        const float x = pl[3*i], y = pl[3*i+1], z = pl[3*i+2];
        const float w = fmaf(x, x, fmaf(y, y, z*z));   // w >= 0: bit order == numeric order
        sk[i] = ((unsigned long long)__float_as_uint(w) << 32) | (unsigned)i;
    }
    __syncthreads();
    for (int k = 2; k <= NL; k <<= 1) {
        for (int j = k >> 1; j > 0; j >>= 1) {
            for (int i = t; i < NL; i += 1024) {
                const int ixj = i ^ j;
                if (ixj > i) {
                    const bool up = ((i & k) == 0);
                    const unsigned long long a = sk[i], b = sk[ixj];
                    if (up ? (a > b) : (a < b)) { sk[i] = b; sk[ixj] = a; }
                }
            }
            __syncthreads();
        }
    }
    for (int i = t; i < NL; i += 1024) {
        const unsigned long long kv = sk[i];
        const int id = (int)(kv & 0xFFFFFFFFull);
        const float x = pl[3*id], y = pl[3*id+1], z = pl[3*id+2];
        const float w = __uint_as_float((unsigned)(kv >> 32));
        g_SL[i]  = make_float4(-2.0f*x, -2.0f*y, -2.0f*z, w);
        g_sid[i] = id;
    }
}

// ---------- kernel 2: annulus search + interp ----------
__global__ __launch_bounds__(TPB, 1)
void knn_interp_kernel(const float* __restrict__ x,
                       const float* __restrict__ pos_l,
                       const float* __restrict__ pos_h,
                       float* __restrict__ out)
{
    extern __shared__ __align__(16) float4 sT[];   // 64 KB sorted table
    __shared__ int   sIdx[PPB][3];
    __shared__ float sW[PPB][3];

    const int tid   = threadIdx.x;
    const int warp  = tid >> 5;
    const int lane  = tid & 31;
    const int group = lane >> 3;        // 0..3 : point within warp
    const int sub   = lane & 7;         // 0..7 : lane within point-group
    const unsigned gmask = 0xFFu << (group * 8);

    const int hbase = blockIdx.x * PPB;
    const int npts  = min(PPB, NH - hbase);
    const int pl_   = warp * 4 + group;                 // point slot 0..111
    const bool valid = (pl_ < npts);
    const int h = hbase + min(pl_, npts - 1);

    // stage sorted table
    for (int i = tid; i < NL; i += TPB) sT[i] = g_SL[i];

    const float hx = pos_h[3*h+0];
    const float hy = pos_h[3*h+1];
    const float hz = pos_h[3*h+2];
    const float hh2  = fmaf(hx, hx, fmaf(hy, hy, hz*hz));
    const float hlen = sqrtf(hh2);
    __syncthreads();

    // binary search: first index with w >= hh2 (12 fixed iterations, group-uniform)
    int lo = 0, hi = NL;
    #pragma unroll
    for (int it = 0; it < 12; ++it) {
        const int mid = (lo + hi) >> 1;
        if (sT[mid].w < hh2) lo = mid + 1; else hi = mid;
    }
    int up = lo, down = lo - 1;

    // per-lane exact top-3 (same guarded insert as R5..R13)
    float s0 = 3.4e38f, s1 = 3.4e38f, s2 = 3.4e38f;
    int   i0 = 0, i1 = 0, i2 = 0;
    auto insert = [&](float s, int g) {
        if (s < s1) {
            s2 = s1; i2 = i1;
            if (s < s0) { s1 = s0; i1 = i0; s0 = s; i0 = g; }
            else        { s1 = s;  i1 = g; }
        } else { s2 = s; i2 = g; }
    };

    float s2m = 3.4e38f;          // group-min of s2 (valid upper bound on final s2)
    bool done = !valid;

    while (__any_sync(0xFFFFFFFFu, !done)) {
        if (!done) {
            // frontier lower bounds (monotone along each direction)
            float bup2 = 3.4e38f, bdn2 = 3.4e38f;
            if (up < NL) {
                const float du = sqrtf(sT[up].w) - hlen;
                bup2 = (du > 0.0f) ? du * du : 0.0f;
            }
            if (down >= 0) {
                const float dd = hlen - sqrtf(sT[down].w);
                bdn2 = (dd > 0.0f) ? dd * dd : 0.0f;
            }
            const float limit = fmaxf(s2m + hh2, 0.0f) * 1.0001f + 1e-6f;
            if (fminf(bup2, bdn2) > limit) {
                done = true;                   // all remaining candidates proven farther
            } else {
                const bool dirUp = (bup2 <= bdn2);
                if (dirUp) {
                    #pragma unroll
                    for (int c = 0; c < 4; ++c) {
                        const int pos = up + sub + 8*c;
                        if (pos < NL) {
                            const float4 m = sT[pos];
                            const float s = fmaf(m.x, hx, fmaf(m.y, hy, fmaf(m.z, hz, m.w)));
                            if (s < s2) insert(s, pos);
                        }
                    }
                    up += 32;
                } else {
                    #pragma unroll
                    for (int c = 0; c < 4; ++c) {
                        const int pos = down - sub - 8*c;
                        if (pos >= 0) {
                            const float4 m = sT[pos];
                            const float s = fmaf(m.x, hx, fmaf(m.y, hy, fmaf(m.z, hz, m.w)));
                            if (s < s2) insert(s, pos);
                        }
                    }
                    down -= 32;
                }
                // tighten group pruning bound: min of lane s2 over the 8-lane group
                float v = s2;
                v = fminf(v, __shfl_xor_sync(gmask, v, 1));
                v = fminf(v, __shfl_xor_sync(gmask, v, 2));
                v = fminf(v, __shfl_xor_sync(gmask, v, 4));
                s2m = v;
            }
        }
    }

    // merge 8 lanes' top-3 -> group top-3 (butterfly; all lanes converged here)
    #pragma unroll
    for (int d = 4; d >= 1; d >>= 1) {
        const float t0 = __shfl_xor_sync(0xFFFFFFFFu, s0, d);
        const float t1 = __shfl_xor_sync(0xFFFFFFFFu, s1, d);
        const float t2 = __shfl_xor_sync(0xFFFFFFFFu, s2, d);
        const int   j0 = __shfl_xor_sync(0xFFFFFFFFu, i0, d);
        const int   j1 = __shfl_xor_sync(0xFFFFFFFFu, i1, d);
        const int   j2 = __shfl_xor_sync(0xFFFFFFFFu, i2, d);
        if (t0 < s2) insert(t0, j0);
        if (t1 < s2) insert(t1, j1);
        if (t2 < s2) insert(t2, j2);
    }

    // weights: exact d2 recompute from original positions (matches reference)
    if (sub == 0 && valid) {
        const int id[3] = { g_sid[i0], g_sid[i1], g_sid[i2] };
        float w[3], wsum = 0.0f;
        #pragma unroll
        for (int k = 0; k < 3; ++k) {
            const float lx = pos_l[3*id[k]+0];
            const float ly = pos_l[3*id[k]+1];
            const float lz = pos_l[3*id[k]+2];
            const float dx = hx - lx, dy = hy - ly, dz = hz - lz;
            const float d2 = fmaf(dx, dx, fmaf(dy, dy, dz*dz));
            const float wk = 1.0f / fmaxf(d2, 1e-16f);
            w[k] = wk;
            wsum += wk;
        }
        const float inv = 1.0f / wsum;
        sIdx[pl_][0] = id[0]; sIdx[pl_][1] = id[1]; sIdx[pl_][2] = id[2];
        sW[pl_][0] = w[0]*inv; sW[pl_][1] = w[1]*inv; sW[pl_][2] = w[2]*inv;
    }
    __syncthreads();

    // interp: one warp per fine point, float4-coalesced (identical to R13)
    const float4* __restrict__ x4 = reinterpret_cast<const float4*>(x);
    float4* __restrict__ o4 = reinterpret_cast<float4*>(out);
    const int rowq = NF / 4;

    for (int pp = warp; pp < npts; pp += 28) {
        const int hh = hbase + pp;
        const int a = sIdx[pp][0], b = sIdx[pp][1], c = sIdx[pp][2];
        const float w0 = sW[pp][0], w1 = sW[pp][1], w2 = sW[pp][2];
        const float4* __restrict__ ra = x4 + a * rowq;
        const float4* __restrict__ rb = x4 + b * rowq;
        const float4* __restrict__ rc = x4 + c * rowq;
        float4* __restrict__ ro = o4 + hh * rowq;
        #pragma unroll
        for (int ch = lane; ch < rowq; ch += 32) {
            const float4 va = ra[ch];
            const float4 vb = rb[ch];
            const float4 vc = rc[ch];
            float4 r;
            r.x = fmaf(w2, vc.x, fmaf(w1, vb.x, w0 * va.x));
            r.y = fmaf(w2, vc.y, fmaf(w1, vb.y, w0 * va.y));
            r.z = fmaf(w2, vc.z, fmaf(w1, vb.z, w0 * va.z));
            r.w = fmaf(w2, vc.w, fmaf(w1, vb.w, w0 * va.w));
            ro[ch] = r;
        }
    }
}

extern "C" void kernel_launch(void* const* d_in, const int* in_sizes, int n_in,
                              void* d_out, int out_size) {
    // Map inputs by element count:
    //   x: 4096*256 = 1048576, pos_l: 4096*3 = 12288, pos_h: 16384*3 = 49152
    const float* x     = nullptr;
    const float* pos_l = nullptr;
    const float* pos_h = nullptr;
    for (int i = 0; i < n_in; ++i) {
        if      (in_sizes[i] == NL * NF) x     = (const float*)d_in[i];
        else if (in_sizes[i] == NL * 3)  pos_l = (const float*)d_in[i];
        else if (in_sizes[i] == NH * 3)  pos_h = (const float*)d_in[i];
    }
    float* out = (float*)d_out;

    k_sort<<<1, 1024>>>(pos_l);
    cudaFuncSetAttribute(knn_interp_kernel,
                         cudaFuncAttributeMaxDynamicSharedMemorySize, SMEM_BYTES);
    knn_interp_kernel<<<GRID, TPB, SMEM_BYTES>>>(x, pos_l, pos_h, out);
}

// round 16
// speedup vs baseline: 1.8850x; 1.8850x over previous
#include <cuda_runtime.h>
#include <cstdint>

static constexpr int NL    = 4096;    // coarse points
static constexpr int NH    = 16384;   // fine points
static constexpr int NF    = 256;     // features
static constexpr int SLOTS = 128;     // point slots per round
static constexpr int SUBS  = 7;       // candidate slices (warp-uniform: 4 warps/sub)
static constexpr int TPB   = SLOTS * SUBS;  // 896 threads, 28 warps
static constexpr int GRID  = 147;     // 7 x 7 x 3 quantile cells, 1 block per cell
static constexpr int NPAIR = NL / 2;  // 2048 packed candidate pairs
static constexpr int P1    = 512;     // phase-1 pairs (candidates [0,1024))
static constexpr int SCAP  = NPAIR - P1 + 8;  // survivor pair capacity (worst case)
static constexpr int PCAP  = 512;     // per-cell fine-point capacity

// dynamic smem layout (bytes)
static constexpr int OFF_QB   = NPAIR * 16;              // sQA at 0
static constexpr int OFF_SQA  = OFF_QB + NPAIR * 16;     // 65536
static constexpr int OFF_SQB  = OFF_SQA + SCAP * 16;
static constexpr int OFF_PIDX = OFF_SQB + SCAP * 16;
static constexpr int SMEM_BYTES = OFF_PIDX + SCAP * 4;   // ~121 KB

__device__ int g_cnt[GRID];
__device__ int g_pts[GRID * PCAP];

// Gaussian quantile slab bounds: Phi^-1(k/7) and Phi^-1(k/3)
__constant__ float QX[8] = {-1e30f, -1.0675705f, -0.5659488f, -0.1800124f,
                             0.1800124f, 0.5659488f, 1.0675705f, 1e30f};
__constant__ float QZ[4] = {-1e30f, -0.4307273f, 0.4307273f, 1e30f};

// packed f32x2 helpers (sm_103a FFMA2 — PTX-only)
__device__ __forceinline__ uint64_t ffma2(uint64_t a, uint64_t b, uint64_t c) {
    uint64_t d;
    asm("fma.rn.f32x2 %0, %1, %2, %3;" : "=l"(d) : "l"(a), "l"(b), "l"(c));
    return d;
}
__device__ __forceinline__ uint64_t pack2(float lo, float hi) {
    uint64_t r;
    asm("mov.b64 %0, {%1, %2};" : "=l"(r) : "f"(lo), "f"(hi));
    return r;
}
__device__ __forceinline__ void unpack2(float& lo, float& hi, uint64_t v) {
    asm("mov.b64 {%0, %1}, %2;" : "=f"(lo), "=f"(hi) : "l"(v));
}

// ---------- kernel 1: bin fine points into quantile cells ----------
__global__ void k_bin(const float* __restrict__ ph) {
    const int i = blockIdx.x * 256 + threadIdx.x;
    if (i < NH) {
        const float x = ph[3*i], y = ph[3*i+1], z = ph[3*i+2];
        const int cx = (x>=QX[1])+(x>=QX[2])+(x>=QX[3])+(x>=QX[4])+(x>=QX[5])+(x>=QX[6]);
        const int cy = (y>=QX[1])+(y>=QX[2])+(y>=QX[3])+(y>=QX[4])+(y>=QX[5])+(y>=QX[6]);
        const int cz = (z>=QZ[1])+(z>=QZ[2]);
        const int b  = (cx * 7 + cy) * 3 + cz;
        const int pos = atomicAdd(&g_cnt[b], 1);
        if (pos < PCAP) g_pts[b * PCAP + pos] = i;
    }
}

// ---------- kernel 2: pruned knn search + interp ----------
__global__ __launch_bounds__(TPB, 1)
void knn_interp_kernel(const float* __restrict__ x,
                       const float* __restrict__ pos_l,
                       const float* __restrict__ pos_h,
                       float* __restrict__ out)
{
    extern __shared__ __align__(16) char smemBuf[];
    ulonglong2* sQA  = reinterpret_cast<ulonglong2*>(smemBuf);
    ulonglong2* sQB  = reinterpret_cast<ulonglong2*>(smemBuf + OFF_QB);
    ulonglong2* sSQA = reinterpret_cast<ulonglong2*>(smemBuf + OFF_SQA);
    ulonglong2* sSQB = reinterpret_cast<ulonglong2*>(smemBuf + OFF_SQB);
    int*        sPidx= reinterpret_cast<int*>(smemBuf + OFF_PIDX);

    __shared__ float    sMs[SUBS][SLOTS][3];
    __shared__ int      sMi[SUBS][SLOTS][3];
    __shared__ float    sS2[SUBS][SLOTS];
    __shared__ int      sIdx[SLOTS][3];
    __shared__ float    sW[SLOTS][3];
    __shared__ unsigned sU2;
    __shared__ int      sCnt2;

    const int tid  = threadIdx.x;
    const int warp = tid >> 5, lane = tid & 31;
    const int sub  = warp >> 2;          // 0..6 (warp-uniform)
    const int p    = tid - sub * SLOTS;  // 0..127

    const int b  = blockIdx.x;
    const int cz = b % 3, cy = (b / 3) % 7, cx = b / 21;
    const float bxlo = QX[cx], bxhi = QX[cx+1];
    const float bylo = QX[cy], byhi = QX[cy+1];
    const float bzlo = QZ[cz], bzhi = QZ[cz+1];

    const int cnt = min(g_cnt[b], PCAP);

    // stage full candidate table, pair-packed (identical to R13 staging)
    {
        const float2* __restrict__ pl2 = reinterpret_cast<const float2*>(pos_l);
        for (int pj = tid; pj < NPAIR; pj += TPB) {
            const float2 v0 = pl2[3*pj+0];
            const float2 v1 = pl2[3*pj+1];
            const float2 v2 = pl2[3*pj+2];
            const float ax = v0.x, ay = v0.y, az = v1.x;
            const float bx = v1.y, by = v2.x, bz = v2.y;
            const float wa = fmaf(ax, ax, fmaf(ay, ay, az*az));
            const float wb = fmaf(bx, bx, fmaf(by, by, bz*bz));
            sQA[pj] = make_ulonglong2(pack2(-2.0f*ax, -2.0f*bx),
                                      pack2(-2.0f*ay, -2.0f*by));
            sQB[pj] = make_ulonglong2(pack2(-2.0f*az, -2.0f*bz),
                                      pack2(wa, wb));
        }
    }
    __syncthreads();

    for (int r0 = 0; r0 < cnt; r0 += SLOTS) {
        const int npts  = min(SLOTS, cnt - r0);
        const bool valid = (p < npts);
        const int h = g_pts[b * PCAP + r0 + (valid ? p : 0)];

        const float hx = pos_h[3*h+0];
        const float hy = pos_h[3*h+1];
        const float hz = pos_h[3*h+2];
        const float hh2 = fmaf(hx, hx, fmaf(hy, hy, hz*hz));
        const uint64_t hx2 = pack2(hx, hx);
        const uint64_t hy2 = pack2(hy, hy);
        const uint64_t hz2 = pack2(hz, hz);

        if (tid == 0) { sU2 = 0u; sCnt2 = 0; }

        float s0 = 3.4e38f, s1 = 3.4e38f, s2 = 3.4e38f;
        int   i0 = 0, i1 = 0, i2 = 0;
        auto insert = [&](float s, int g) {   // proven R5..R13 guarded insert
            if (s < s1) {
                s2 = s1; i2 = i1;
                if (s < s0) { s1 = s0; i1 = i0; s0 = s; i0 = g; }
                else        { s1 = s;  i1 = g; }
            } else { s2 = s; i2 = g; }
        };

        // ---- phase 1: exact scan of candidates [0,1024) ----
        if (valid) {
            const int b1 = (sub * P1) / SUBS, e1 = ((sub + 1) * P1) / SUBS;
            #pragma unroll 4
            for (int j = b1; j < e1; ++j) {
                const ulonglong2 qa = sQA[j];
                const ulonglong2 qb = sQB[j];
                uint64_t t = ffma2(qb.x, hz2, qb.y);
                t = ffma2(qa.y, hy2, t);
                t = ffma2(qa.x, hx2, t);
                float sa, sb; unpack2(sa, sb, t);
                if (sa < s2) insert(sa, 2*j);
                if (sb < s2) insert(sb, 2*j + 1);
            }
        }
        sS2[sub][p] = s2;
        __syncthreads();

        // ---- U^2 = max_p (min_sub s2 + |h|^2): upper bound on 3rd-NN dist^2 ----
        if (tid < npts) {
            float m = sS2[0][tid];
            #pragma unroll
            for (int ss = 1; ss < SUBS; ++ss) m = fminf(m, sS2[ss][tid]);
            const float u2 = fmaxf(m + hh2, 0.0f);
            atomicMax(&sU2, __float_as_uint(u2));   // u2 >= 0: uint order == float order
        }
        __syncthreads();
        const float U2f = __uint_as_float(sU2) * 1.0002f + 1e-5f;

        // ---- cooperative filter of pairs [512,2048) against cell box ----
        for (int j = P1 + tid; j < NPAIR; j += TPB) {
            const ulonglong2 qa = sQA[j];
            const ulonglong2 qb = sQB[j];
            float xa, xb, ya, yb, za, zb;
            unpack2(xa, xb, qa.x); unpack2(ya, yb, qa.y); unpack2(za, zb, qb.x);
            const float lxa = -0.5f*xa, lya = -0.5f*ya, lza = -0.5f*za;
            const float lxb = -0.5f*xb, lyb = -0.5f*yb, lzb = -0.5f*zb;
            const float exa = fmaxf(fmaxf(bxlo-lxa, lxa-bxhi), 0.0f);
            const float eya = fmaxf(fmaxf(bylo-lya, lya-byhi), 0.0f);
            const float eza = fmaxf(fmaxf(bzlo-lza, lza-bzhi), 0.0f);
            const float exb = fmaxf(fmaxf(bxlo-lxb, lxb-bxhi), 0.0f);
            const float eyb = fmaxf(fmaxf(bylo-lyb, lyb-byhi), 0.0f);
            const float ezb = fmaxf(fmaxf(bzlo-lzb, lzb-bzhi), 0.0f);
            const float da = fmaf(exa, exa, fmaf(eya, eya, eza*eza));
            const float db = fmaf(exb, exb, fmaf(eyb, eyb, ezb*ezb));
            if (fminf(da, db) <= U2f) {
                const int k = atomicAdd(&sCnt2, 1);
                sSQA[k] = qa; sSQB[k] = qb; sPidx[k] = j;
            }
        }
        __syncthreads();

        const int scnt   = sCnt2;
        const int padded = ((scnt + SUBS - 1) / SUBS) * SUBS;
        for (int k = scnt + tid; k < padded; k += TPB) {   // sentinels: huge score
            sSQA[k] = make_ulonglong2(0ull, 0ull);
            sSQB[k] = make_ulonglong2(0ull, pack2(1e37f, 1e37f));
            sPidx[k] = P1;
        }
        __syncthreads();

        // ---- phase 2: scan survivors (same registers, same insert) ----
        if (valid && padded > 0) {
            const int PS = padded / SUBS;
            const int b2 = sub * PS, e2 = b2 + PS;
            #pragma unroll 4
            for (int k = b2; k < e2; ++k) {
                const ulonglong2 qa = sSQA[k];
                const ulonglong2 qb = sSQB[k];
                uint64_t t = ffma2(qb.x, hz2, qb.y);
                t = ffma2(qa.y, hy2, t);
                t = ffma2(qa.x, hx2, t);
                float sa, sb; unpack2(sa, sb, t);
                if (sa < s2) insert(sa, 65536 + 2*k);
                if (sb < s2) insert(sb, 65536 + 2*k + 1);
            }
        }

        sMs[sub][p][0] = s0; sMs[sub][p][1] = s1; sMs[sub][p][2] = s2;
        sMi[sub][p][0] = i0; sMi[sub][p][1] = i1; sMi[sub][p][2] = i2;
        __syncthreads();

        // ---- merge subs -> final top-3; exact-d2 weights ----
        if (tid < npts) {   // these threads are sub==0, p==tid: (hx,hy,hz) correct
            float b0 = 3.4e38f, b1 = 3.4e38f, b2 = 3.4e38f;
            int   j0 = 0, j1 = 0, j2 = 0;
            #pragma unroll
            for (int ss = 0; ss < SUBS; ++ss) {
                #pragma unroll
                for (int k = 0; k < 3; ++k) {
                    const float s = sMs[ss][tid][k];
                    const int   g = sMi[ss][tid][k];
                    if (s < b2) {
                        if (s < b1) {
                            b2 = b1; j2 = j1;
                            if (s < b0) { b1 = b0; j1 = j0; b0 = s; j0 = g; }
                            else        { b1 = s;  j1 = g; }
                        } else { b2 = s; j2 = g; }
                    }
                }
            }
            auto decode = [&](int g) -> int {
                return (g >= 65536) ? (2 * sPidx[(g - 65536) >> 1] + (g & 1)) : g;
            };
            const int id[3] = { decode(j0), decode(j1), decode(j2) };
            float w[3], wsum = 0.0f;
            #pragma unroll
            for (int k = 0; k < 3; ++k) {
                const float lx = pos_l[3*id[k]+0];
                const float ly = pos_l[3*id[k]+1];
                const float lz = pos_l[3*id[k]+2];
                const float dx = hx - lx, dy = hy - ly, dz = hz - lz;
                const float d2 = fmaf(dx, dx, fmaf(dy, dy, dz*dz));
                const float wk = 1.0f / fmaxf(d2, 1e-16f);
                w[k] = wk;
                wsum += wk;
            }
            const float inv = 1.0f / wsum;
            sIdx[tid][0] = id[0]; sIdx[tid][1] = id[1]; sIdx[tid][2] = id[2];
            sW[tid][0] = w[0]*inv; sW[tid][1] = w[1]*inv; sW[tid][2] = w[2]*inv;
        }
        __syncthreads();

        // ---- interp: one warp per fine point, float4-coalesced ----
        const float4* __restrict__ x4 = reinterpret_cast<const float4*>(x);
        float4* __restrict__ o4 = reinterpret_cast<float4*>(out);
        const int rowq = NF / 4;
        for (int pp = warp; pp < npts; pp += 28) {
            const int hh = g_pts[b * PCAP + r0 + pp];
            const int a = sIdx[pp][0], bb = sIdx[pp][1], c = sIdx[pp][2];
            const float w0 = sW[pp][0], w1 = sW[pp][1], w2 = sW[pp][2];
            const float4* __restrict__ ra = x4 + a  * rowq;
            const float4* __restrict__ rb = x4 + bb * rowq;
            const float4* __restrict__ rc = x4 + c  * rowq;
            float4* __restrict__ ro = o4 + hh * rowq;
            #pragma unroll
            for (int ch = lane; ch < rowq; ch += 32) {
                const float4 va = ra[ch];
                const float4 vb = rb[ch];
                const float4 vc = rc[ch];
                float4 r;
                r.x = fmaf(w2, vc.x, fmaf(w1, vb.x, w0 * va.x));
                r.y = fmaf(w2, vc.y, fmaf(w1, vb.y, w0 * va.y));
                r.z = fmaf(w2, vc.z, fmaf(w1, vb.z, w0 * va.z));
                r.w = fmaf(w2, vc.w, fmaf(w1, vb.w, w0 * va.w));
                ro[ch] = r;
            }
        }
        __syncthreads();   // protect shared state before next round
    }

    if (tid == 0) g_cnt[b] = 0;   // self-reset for next graph replay
}

extern "C" void kernel_launch(void* const* d_in, const int* in_sizes, int n_in,
                              void* d_out, int out_size) {
    // Map inputs by element count:
    //   x: 4096*256 = 1048576, pos_l: 4096*3 = 12288, pos_h: 16384*3 = 49152
    const float* x     = nullptr;
    const float* pos_l = nullptr;
    const float* pos_h = nullptr;
    for (int i = 0; i < n_in; ++i) {
        if      (in_sizes[i] == NL * NF) x     = (const float*)d_in[i];
        else if (in_sizes[i] == NL * 3)  pos_l = (const float*)d_in[i];
        else if (in_sizes[i] == NH * 3)  pos_h = (const float*)d_in[i];
    }
    float* out = (float*)d_out;

    k_bin<<<(NH + 255) / 256, 256>>>(pos_h);
    cudaFuncSetAttribute(knn_interp_kernel,
                         cudaFuncAttributeMaxDynamicSharedMemorySize, SMEM_BYTES);
    knn_interp_kernel<<<GRID, TPB, SMEM_BYTES>>>(x, pos_l, pos_h, out);
}

// round 17
// speedup vs baseline: 2.8980x; 1.5374x over previous
#include <cuda_runtime.h>
#include <cstdint>

static constexpr int NL   = 4096;    // coarse points
static constexpr int NH   = 16384;   // fine points
static constexpr int NF   = 256;     // features
static constexpr int PPB  = 112;     // fine points per block (147 blocks -> 147/148 SMs)
static constexpr int SUBS = 8;       // candidate slices
static constexpr int TPB  = PPB * SUBS;   // 896 threads, 28 warps
static constexpr int GRID = (NH + PPB - 1) / PPB;  // 147
static constexpr int NPAIR = NL / 2;       // 2048 staged pairs (whole table, 64 KB)
static constexpr int WPAIR = NPAIR / SUBS; // 256 pairs per sub
static constexpr int SMEM_BYTES = NL * 16; // 64 KB dynamic

// packed f32x2 helpers (sm_103a FFMA2 — PTX-only, ptxas never auto-fuses)
__device__ __forceinline__ uint64_t ffma2(uint64_t a, uint64_t b, uint64_t c) {
    uint64_t d;
    asm("fma.rn.f32x2 %0, %1, %2, %3;" : "=l"(d) : "l"(a), "l"(b), "l"(c));
    return d;
}
__device__ __forceinline__ uint64_t pack2(float lo, float hi) {
    uint64_t r;
    asm("mov.b64 %0, {%1, %2};" : "=l"(r) : "f"(lo), "f"(hi));
    return r;
}
__device__ __forceinline__ void unpack2(float& lo, float& hi, uint64_t v) {
    asm("mov.b64 {%0, %1}, %2;" : "=f"(lo), "=f"(hi) : "l"(v));
}

__global__ __launch_bounds__(TPB, 1)
void knn_interp_kernel(const float* __restrict__ x,
                       const float* __restrict__ pos_l,
                       const float* __restrict__ pos_h,
                       float* __restrict__ out)
{
    // 64 KB dynamic buffer: whole pair-packed candidate table during the scan,
    // then reused (after a barrier) for the per-sub merge arrays (~21.5 KB).
    extern __shared__ __align__(16) char smemBuf[];
    __shared__ int   sIdx[PPB][3];
    __shared__ float sW[PPB][3];

    // QA[j] = (xpair, ypair), QB[j] = (zpair, wpair); x=-2lx etc., w=|l|^2
    ulonglong2* sQA = reinterpret_cast<ulonglong2*>(smemBuf);               // 32 KB
    ulonglong2* sQB = reinterpret_cast<ulonglong2*>(smemBuf + NPAIR*16);    // 32 KB
    float (*sMs)[PPB][3] = reinterpret_cast<float (*)[PPB][3]>(smemBuf);
    int   (*sMi)[PPB][3] = reinterpret_cast<int   (*)[PPB][3]>(smemBuf + SUBS*PPB*3*4);

    const int tid  = threadIdx.x;
    const int sub  = tid / PPB;        // 0..7 : candidate slice
    const int p    = tid - sub * PPB;  // 0..111 : fine point within block
    const int hbase = blockIdx.x * PPB;
    const int npts = min(PPB, NH - hbase);        // tail block: 32 valid points
    const int h    = hbase + min(p, npts - 1);    // clamp: invalid lanes discarded later

    const float hx = pos_h[3*h+0];
    const float hy = pos_h[3*h+1];
    const float hz = pos_h[3*h+2];
    const uint64_t hx2 = pack2(hx, hx);
    const uint64_t hy2 = pack2(hy, hy);
    const uint64_t hz2 = pack2(hz, hz);

    // stage the whole candidate table once (float2-vectorized gmem reads)
    {
        const float2* __restrict__ pl2 = reinterpret_cast<const float2*>(pos_l);
        for (int pj = tid; pj < NPAIR; pj += TPB) {
            const float2 v0 = pl2[3*pj+0];   // ax ay
            const float2 v1 = pl2[3*pj+1];   // az bx
            const float2 v2 = pl2[3*pj+2];   // by bz
            const float ax = v0.x, ay = v0.y, az = v1.x;
            const float bx = v1.y, by = v2.x, bz = v2.y;
            const float wa = fmaf(ax, ax, fmaf(ay, ay, az*az));
            const float wb = fmaf(bx, bx, fmaf(by, by, bz*bz));
            sQA[pj] = make_ulonglong2(pack2(-2.0f*ax, -2.0f*bx),
                                      pack2(-2.0f*ay, -2.0f*by));
            sQB[pj] = make_ulonglong2(pack2(-2.0f*az, -2.0f*bz),
                                      pack2(wa, wb));
        }
    }
    __syncthreads();

    // Partial top-3 by score = |l|^2 - 2 h.l (selection identical to R13)
    float s0 = 3.4e38f, s1 = 3.4e38f, s2 = 3.4e38f;
    int   i0 = 0, i1 = 0, i2 = 0;

    // Branchless sorted-3 update. Called only under the guard (s < s2).
    // Produces exactly the sequential-insert result for all inputs (incl. ties):
    //   s2' = max(s1, s);  s1' = max(s0, min(s1, s));  s0' = min(s0, s)
    auto insert = [&](float s, int g) {
        const bool lt1 = s < s1;
        const bool lt0 = s < s0;
        const float ns2 = fmaxf(s1, s);
        const int   ni2 = lt1 ? i1 : g;
        const float ns1 = fmaxf(s0, fminf(s1, s));
        const int   ni1 = lt1 ? (lt0 ? i0 : g) : i1;
        const float ns0 = fminf(s0, s);
        const int   ni0 = lt0 ? g : i0;
        s2 = ns2; i2 = ni2; s1 = ns1; i1 = ni1; s0 = ns0; i0 = ni0;
    };

    {
        const int pb = sub * WPAIR;            // warp-level LDS broadcast/coalesced
        const int gb = 2 * pb;
        #pragma unroll 8
        for (int jp = 0; jp < WPAIR; ++jp) {
            const ulonglong2 qa = sQA[pb + jp];   // (xpair, ypair)
            const ulonglong2 qb = sQB[pb + jp];   // (zpair, wpair)
            uint64_t t = ffma2(qb.x, hz2, qb.y);
            t = ffma2(qa.y, hy2, t);
            t = ffma2(qa.x, hx2, t);
            float sa, sb;
            unpack2(sa, sb, t);
            const int g = gb + 2*jp;
            if (sa < s2) insert(sa, g);       // sequential order preserved:
            if (sb < s2) insert(sb, g + 1);   // a first, then b
        }
    }

    __syncthreads();   // all reads of sQA/sQB done -> safe to alias as merge buffers
    sMs[sub][p][0] = s0; sMs[sub][p][1] = s1; sMs[sub][p][2] = s2;
    sMi[sub][p][0] = i0; sMi[sub][p][1] = i1; sMi[sub][p][2] = i2;
    __syncthreads();

    // Merge 8 partial top-3s -> final top-3; exact-d2 weights.
    // Threads tid<npts have p==tid, so (hx,hy,hz) already hold this point's coords.
    if (tid < npts) {
        float b0 = 3.4e38f, b1 = 3.4e38f, b2 = 3.4e38f;
        int   j0 = 0, j1 = 0, j2 = 0;
        #pragma unroll
        for (int ss = 0; ss < SUBS; ++ss) {
            #pragma unroll
            for (int k = 0; k < 3; ++k) {
                const float s = sMs[ss][tid][k];
                const int   g = sMi[ss][tid][k];
                if (s < b2) {
                    if (s < b1) {
                        b2 = b1; j2 = j1;
                        if (s < b0) { b1 = b0; j1 = j0; b0 = s; j0 = g; }
                        else        { b1 = s;  j1 = g; }
                    } else { b2 = s; j2 = g; }
                }
            }
        }
        // Exact squared distances for the 3 selected (matches reference recompute)
        const int id[3] = {j0, j1, j2};
        float w[3], wsum = 0.0f;
        #pragma unroll
        for (int k = 0; k < 3; ++k) {
            const float lx = pos_l[3*id[k]+0];
            const float ly = pos_l[3*id[k]+1];
            const float lz = pos_l[3*id[k]+2];
            const float dx = hx - lx, dy = hy - ly, dz = hz - lz;
            const float d2 = fmaf(dx, dx, fmaf(dy, dy, dz*dz));
            const float wk = 1.0f / fmaxf(d2, 1e-16f);
            w[k] = wk;
            wsum += wk;
        }
        const float inv = 1.0f / wsum;
        sIdx[tid][0] = id[0]; sIdx[tid][1] = id[1]; sIdx[tid][2] = id[2];
        sW[tid][0] = w[0]*inv; sW[tid][1] = w[1]*inv; sW[tid][2] = w[2]*inv;
    }
    __syncthreads();

    // Phase B: gather + weighted sum. One warp per fine point, float4-coalesced.
    const int warp = tid >> 5, lane = tid & 31;   // 28 warps
    const float4* __restrict__ x4 = reinterpret_cast<const float4*>(x);
    float4* __restrict__ o4 = reinterpret_cast<float4*>(out);
    const int rowq = NF / 4;   // 64 float4 per feature row

    for (int pp = warp; pp < npts; pp += 28) {
        const int hh = hbase + pp;
        const int a = sIdx[pp][0], b = sIdx[pp][1], c = sIdx[pp][2];
        const float w0 = sW[pp][0], w1 = sW[pp][1], w2 = sW[pp][2];
        const float4* __restrict__ ra = x4 + a * rowq;
        const float4* __restrict__ rb = x4 + b * rowq;
        const float4* __restrict__ rc = x4 + c * rowq;
        float4* __restrict__ ro = o4 + hh * rowq;
        #pragma unroll
        for (int ch = lane; ch < rowq; ch += 32) {
            const float4 va = ra[ch];
            const float4 vb = rb[ch];
            const float4 vc = rc[ch];
            float4 r;
            r.x = fmaf(w2, vc.x, fmaf(w1, vb.x, w0 * va.x));
            r.y = fmaf(w2, vc.y, fmaf(w1, vb.y, w0 * va.y));
            r.z = fmaf(w2, vc.z, fmaf(w1, vb.z, w0 * va.z));
            r.w = fmaf(w2, vc.w, fmaf(w1, vb.w, w0 * va.w));
            ro[ch] = r;
        }
    }
}

extern "C" void kernel_launch(void* const* d_in, const int* in_sizes, int n_in,
                              void* d_out, int out_size) {
    // Map inputs by element count:
    //   x: 4096*256 = 1048576, pos_l: 4096*3 = 12288, pos_h: 16384*3 = 49152
    const float* x     = nullptr;
    const float* pos_l = nullptr;
    const float* pos_h = nullptr;
    for (int i = 0; i < n_in; ++i) {
        if      (in_sizes[i] == NL * NF) x     = (const float*)d_in[i];
        else if (in_sizes[i] == NL * 3)  pos_l = (const float*)d_in[i];
        else if (in_sizes[i] == NH * 3)  pos_h = (const float*)d_in[i];
    }
    float* out = (float*)d_out;
    cudaFuncSetAttribute(knn_interp_kernel,
                         cudaFuncAttributeMaxDynamicSharedMemorySize, SMEM_BYTES);
    knn_interp_kernel<<<GRID, TPB, SMEM_BYTES>>>(x, pos_l, pos_h, out);
}